// round 15
// baseline (speedup 1.0000x reference)
#include <cuda_runtime.h>
#include <cuda_bf16.h>
#include <cstdint>

// ---------------- problem dims ----------------
#define TT 1024
#define BB 8
#define DD 1024
#define HH 16
#define ROWS 8192
#define SEGC 8388608u
#define KC 3072                 // concatenated split-bf16 K (hi|hi|lo vs hi|lo|hi)

typedef unsigned long long ull;

// ---------------- device scratch ----------------
__device__ float g_proj[5ull * SEGC];     // q,k,v,apre,bpre (fp32)
__device__ float g_alpha[ROWS * HH];
__device__ float g_beta[ROWS * HH];
__device__ __align__(16) __nv_bfloat16 g_xcat[(size_t)ROWS * KC];   // 48 MB
__device__ __align__(16) __nv_bfloat16 g_wcat[(size_t)5120 * KC];   // 30 MB

// ---------------- helpers ----------------
__device__ __forceinline__ uint32_t smem_u32(const void* p) {
    uint32_t a;
    asm("{ .reg .u64 t; cvta.to.shared.u64 t, %1; cvt.u32.u64 %0, t; }" : "=r"(a) : "l"(p));
    return a;
}
__device__ __forceinline__ void cpa16(uint32_t dst, const void* src) {
    asm volatile("cp.async.cg.shared.global [%0], [%1], 16;" :: "r"(dst), "l"(src));
}
#define CP_COMMIT() asm volatile("cp.async.commit_group;")
#define CP_WAIT2()  asm volatile("cp.async.wait_group 2;")

__device__ __forceinline__ void ldm4(uint32_t* r, uint32_t a) {
    asm volatile("ldmatrix.sync.aligned.m8n8.x4.shared.b16 {%0,%1,%2,%3}, [%4];"
        : "=r"(r[0]), "=r"(r[1]), "=r"(r[2]), "=r"(r[3]) : "r"(a));
}
__device__ __forceinline__ void mma16816(float* d, const uint32_t* a, uint32_t b0, uint32_t b1) {
    asm volatile(
        "mma.sync.aligned.m16n8k16.row.col.f32.bf16.bf16.f32 "
        "{%0,%1,%2,%3},{%4,%5,%6,%7},{%8,%9},{%0,%1,%2,%3};"
        : "+f"(d[0]), "+f"(d[1]), "+f"(d[2]), "+f"(d[3])
        : "r"(a[0]), "r"(a[1]), "r"(a[2]), "r"(a[3]), "r"(b0), "r"(b1));
}

// packed f32x2 (sm_100+ FFMA2)
#define FMA2(d, a, b, c) asm("fma.rn.f32x2 %0, %1, %2, %3;" : "=l"(d) : "l"(a), "l"(b), "l"(c))
#define MUL2(d, a, b)    asm("mul.rn.f32x2 %0, %1, %2;"     : "=l"(d) : "l"(a), "l"(b))
#define PK2(d, x, y)     asm("mov.b64 %0, {%1, %2};"        : "=l"(d) : "f"(x), "f"(y))
#define UNPK2(x, y, d)   asm("mov.b64 {%0, %1}, %2;"        : "=f"(x), "=f"(y) : "l"(d))

// split one float into bf16 hi + bf16 lo
__device__ __forceinline__ void split2(float f0, float f1, uint32_t& hw, uint32_t& lw) {
    __nv_bfloat16 h0 = __float2bfloat16(f0);
    __nv_bfloat16 h1 = __float2bfloat16(f1);
    __nv_bfloat16 l0 = __float2bfloat16(f0 - __bfloat162float(h0));
    __nv_bfloat16 l1 = __float2bfloat16(f1 - __bfloat162float(h1));
    hw = (uint32_t)__bfloat16_as_ushort(h0) | ((uint32_t)__bfloat16_as_ushort(h1) << 16);
    lw = (uint32_t)__bfloat16_as_ushort(l0) | ((uint32_t)__bfloat16_as_ushort(l1) << 16);
}

// 16-float packed dot (x,y are 8 x f32x2)
__device__ __forceinline__ float dot16(const ull* x, const ull* y) {
    ull d0, d1;
    MUL2(d0, x[0], y[0]); MUL2(d1, x[1], y[1]);
    FMA2(d0, x[2], y[2], d0); FMA2(d1, x[3], y[3], d1);
    FMA2(d0, x[4], y[4], d0); FMA2(d1, x[5], y[5], d1);
    FMA2(d0, x[6], y[6], d0); FMA2(d1, x[7], y[7], d1);
    float ax, ay, bx, by; UNPK2(ax, ay, d0); UNPK2(bx, by, d1);
    return (ax + bx) + (ay + by);
}
__device__ __forceinline__ void ld16(ull* dst, const float* p) {
    const ulonglong2* u = (const ulonglong2*)p;
    ulonglong2 u0 = u[0], u1 = u[1], u2 = u[2], u3 = u[3];
    dst[0] = u0.x; dst[1] = u0.y; dst[2] = u1.x; dst[3] = u1.y;
    dst[4] = u2.x; dst[5] = u2.y; dst[6] = u3.x; dst[7] = u3.y;
}
__device__ __forceinline__ float redq(float r) {
    r += __shfl_xor_sync(0xffffffffu, r, 1);
    r += __shfl_xor_sync(0xffffffffu, r, 2);
    return r;
}

// =====================================================================
// pack_all: fused pack_x + pack_w (unchanged).
// =====================================================================
__global__ __launch_bounds__(256)
void pack_all(const float* __restrict__ x,
              const float* __restrict__ W0, const float* __restrict__ W1,
              const float* __restrict__ W2, const float* __restrict__ W3,
              const float* __restrict__ W4)
{
    unsigned idx = blockIdx.x * 256 + threadIdx.x;
    if (idx < 1048576u) {
        unsigned e = idx * 8;
        unsigned row = e >> 10, col = e & 1023;
        float4 f0 = *(const float4*)(x + e);
        float4 f1 = *(const float4*)(x + e + 4);
        uint4 hi, lo;
        split2(f0.x, f0.y, hi.x, lo.x);
        split2(f0.z, f0.w, hi.y, lo.y);
        split2(f1.x, f1.y, hi.z, lo.z);
        split2(f1.z, f1.w, hi.w, lo.w);
        __nv_bfloat16* base = g_xcat + (size_t)row * KC;
        *(uint4*)(base + col)        = hi;
        *(uint4*)(base + col + 1024) = hi;
        *(uint4*)(base + col + 2048) = lo;
    } else {
        unsigned j = idx - 1048576u;
        unsigned e = j * 8;
        unsigned seg = e >> 20;
        unsigned n = (e >> 10) & 1023, k = e & 1023;
        const float* W = (seg == 0) ? W0 : (seg == 1) ? W1 : (seg == 2) ? W2
                         : (seg == 3) ? W3 : W4;
        const float* src = W + (size_t)n * 1024 + k;
        float4 f0 = *(const float4*)(src);
        float4 f1 = *(const float4*)(src + 4);
        uint4 hi, lo;
        split2(f0.x, f0.y, hi.x, lo.x);
        split2(f0.z, f0.w, hi.y, lo.y);
        split2(f1.x, f1.y, hi.z, lo.z);
        split2(f1.z, f1.w, hi.w, lo.w);
        __nv_bfloat16* base = g_wcat + (size_t)(seg * 1024 + n) * KC;
        *(uint4*)(base + k)        = hi;
        *(uint4*)(base + k + 1024) = lo;
        *(uint4*)(base + k + 2048) = hi;
    }
}

// =====================================================================
// gemm_mma: EXACT R8 config (best measured: 752.9us, tensor 56.6%).
// =====================================================================
#define STG 20480

__global__ __launch_bounds__(256, 2)
void gemm_mma()
{
    extern __shared__ __align__(16) unsigned char sm[];
    const uint32_t smb = smem_u32(sm);

    const int bid = blockIdx.x;
    const int mt = bid / 40, nt = bid % 40;
    const int tid = threadIdx.x;
    const int lane = tid & 31, wid = tid >> 5;
    const int wm = wid & 1, wn = wid >> 1;

    const int lrow = tid >> 2, lch = tid & 3;
    const __nv_bfloat16* Ag = g_xcat + (size_t)(mt * 128 + lrow) * KC + lch * 8;
    const __nv_bfloat16* Bg = g_wcat + (size_t)(nt * 128 + lrow) * KC + lch * 8;
    const uint32_t sA = smb + lrow * 80 + lch * 16;
    const uint32_t sB = smb + 10240 + lrow * 80 + lch * 16;

    auto load = [&](int it, int stage) {
        const uint32_t off = stage * STG;
        const __nv_bfloat16* ag = Ag + it * 32;
        const __nv_bfloat16* bg = Bg + it * 32;
        cpa16(sA + off,           ag);
        cpa16(sA + off + 64 * 80, ag + (size_t)64 * KC);
        cpa16(sB + off,           bg);
        cpa16(sB + off + 64 * 80, bg + (size_t)64 * KC);
    };

    uint32_t aAddr[4], bAddr[2];
#pragma unroll
    for (int f = 0; f < 4; f++)
        aAddr[f] = smb + (wm * 64 + f * 16 + (lane & 15)) * 80 + (lane >> 4) * 16;
#pragma unroll
    for (int x = 0; x < 2; x++)
        bAddr[x] = smb + 10240 + (wn * 32 + x * 16 + (lane & 15)) * 80 + (lane >> 4) * 16;

    float acc[4][4][4];
#pragma unroll
    for (int f = 0; f < 4; f++)
#pragma unroll
        for (int g = 0; g < 4; g++)
#pragma unroll
            for (int i = 0; i < 4; i++) acc[f][g][i] = 0.f;

    load(0, 0); CP_COMMIT();
    load(1, 1); CP_COMMIT();
    load(2, 2); CP_COMMIT();

    const int NIT = KC / 32;    // 96
    for (int it = 0; it < NIT; it++) {
        CP_WAIT2();
        __syncthreads();
        if (it + 3 < NIT) load(it + 3, (it + 3) & 3);
        CP_COMMIT();

        const uint32_t st = (it & 3) * STG;
#pragma unroll
        for (int ks = 0; ks < 2; ks++) {
            uint32_t af[4][4], bf[2][4];
#pragma unroll
            for (int f = 0; f < 4; f++) ldm4(af[f], aAddr[f] + st + ks * 32);
#pragma unroll
            for (int x = 0; x < 2; x++) ldm4(bf[x], bAddr[x] + st + ks * 32);
#pragma unroll
            for (int f = 0; f < 4; f++) {
#pragma unroll
                for (int g = 0; g < 4; g++) {
                    const uint32_t b0 = bf[g >> 1][g & 1];
                    const uint32_t b1 = bf[g >> 1][(g & 1) + 2];
                    mma16816(acc[f][g], af[f], b0, b1);
                }
            }
        }
    }

    const int seg = nt >> 3;
    float* op = g_proj + (size_t)seg * SEGC;
    const int rbase = mt * 128 + wm * 64 + (lane >> 2);
    const int cbase = (nt & 7) * 128 + wn * 32 + (lane & 3) * 2;
#pragma unroll
    for (int f = 0; f < 4; f++) {
#pragma unroll
        for (int g = 0; g < 4; g++) {
            const int r = rbase + f * 16;
            const int c = cbase + g * 8;
            float2 v0 = make_float2(acc[f][g][0], acc[f][g][1]);
            float2 v1 = make_float2(acc[f][g][2], acc[f][g][3]);
            *(float2*)(op + (size_t)r * 1024 + c)       = v0;
            *(float2*)(op + (size_t)(r + 8) * 1024 + c) = v1;
        }
    }
}

// =====================================================================
// postproc: unchanged.
// =====================================================================
__device__ __forceinline__ float sigf(float x) { return 1.0f / (1.0f + expf(-x)); }

__global__ __launch_bounds__(256)
void postproc(const float* __restrict__ b_alpha, const float* __restrict__ b_beta)
{
    const int wid = threadIdx.x >> 5;
    const int lane = threadIdx.x & 31;
    const int gb = blockIdx.x * 8 + wid;   // tb*16 + h
    const int h = gb & 15;
    const size_t row = (size_t)(gb >> 4) * DD + h * 64 + lane * 2;

    float2 q  = *(float2*)(g_proj + row);
    float2 k  = *(float2*)(g_proj + (size_t)SEGC + row);
    float2 ap = *(float2*)(g_proj + 3ull * SEGC + row);
    float2 bp = *(float2*)(g_proj + 4ull * SEGC + row);
    float2 ba = *(const float2*)(b_alpha + h * 64 + lane * 2);
    float2 bbv = *(const float2*)(b_beta + h * 64 + lane * 2);

    float sq = fmaf(q.x, q.x, q.y * q.y);
    float sk = fmaf(k.x, k.x, k.y * k.y);
    float sa = sigf(ap.x + ba.x) + sigf(ap.y + ba.y);
    float sb = sigf(bp.x + bbv.x) + sigf(bp.y + bbv.y);
#pragma unroll
    for (int m = 16; m; m >>= 1) {
        sq += __shfl_xor_sync(0xffffffffu, sq, m);
        sk += __shfl_xor_sync(0xffffffffu, sk, m);
        sa += __shfl_xor_sync(0xffffffffu, sa, m);
        sb += __shfl_xor_sync(0xffffffffu, sb, m);
    }
    const float qi = 1.0f / fmaxf(sqrtf(sq), 1e-12f);
    const float ki = 1.0f / fmaxf(sqrtf(sk), 1e-12f);
    q.x *= qi; q.y *= qi;
    k.x *= ki; k.y *= ki;
    *(float2*)(g_proj + row) = q;
    *(float2*)(g_proj + (size_t)SEGC + row) = k;
    if (lane == 0) {
        g_alpha[gb] = sa * (1.0f / 64.0f);
        g_beta[gb]  = sb * (1.0f / 64.0f);
    }
}

// =====================================================================
// scan v8: lookahead-4 pending pipeline.
//   P_j = S_{t-1}.k_{t+j} (j=0..2), C = incoming slot (j=3):
//   P_j' = a*P_{j+1} + coef*kk_{j+1}[t];  C_{t+1} = a_t*ddr_t + coef_t*kk4[t]
//   ddr_t = S_{t-1}.k_{t+4}  (dot + shfl have a FULL STEP of slack)
// Serial chain: coef -> P0' -> sk -> coef  (~12 cyc). kk table built in
// a smem prologue per CTA. K ring 8 (ddr operand age 4 steps), Q ring 2,
// v/a/b/kk rings 4/2. Grid 256 (bh x half), block 128 (32 rows x 4 qu).
// =====================================================================
#define LK(S, t) ld16(K[S], kb + (size_t)(t) * 8192 + qu * 16)
#define LQ(S, t) ld16(Q[S], qb + (size_t)(t) * 8192 + qu * 16)
#define LV(S, t) { va[S] = vb[(size_t)(t) * 8192]; \
                   aa[S] = g_alpha[(t) * 128 + bh]; \
                   bba[S] = g_beta[(t) * 128 + bh]; }

#define STEP(I, tt) { \
    const float4 kk = kknxt; \
    { int nx = (tt) + 1; if (nx > 1023) nx = 1023; kknxt = smkk[nx]; } \
    const float a = aa[(I) & 3], be = bba[(I) & 3], vv = va[(I) & 3]; \
    const float C = fmaf(coefp, kk4p, ap * ddrp); \
    const float sk = P0; \
    const float coef = be * fmaf(-a, sk, vv); \
    P0 = fmaf(coef, kk.x, a * P1); \
    P1 = fmaf(coef, kk.y, a * P2); \
    P2 = fmaf(coef, kk.z, a * C); \
    ap = a; coefp = coef; kk4p = kk.w; \
    ddrp = redq(dot16(s, K[((I) + 4) & 7])); \
    ull a2, c2; PK2(a2, a, a); PK2(c2, coef, coef); \
    ull o0, o1, tmp; \
    MUL2(tmp, a2, s[0]); FMA2(s[0], c2, K[(I)][0], tmp); MUL2(o0, s[0], Q[(I) & 1][0]); \
    MUL2(tmp, a2, s[1]); FMA2(s[1], c2, K[(I)][1], tmp); MUL2(o1, s[1], Q[(I) & 1][1]); \
    MUL2(tmp, a2, s[2]); FMA2(s[2], c2, K[(I)][2], tmp); FMA2(o0, s[2], Q[(I) & 1][2], o0); \
    MUL2(tmp, a2, s[3]); FMA2(s[3], c2, K[(I)][3], tmp); FMA2(o1, s[3], Q[(I) & 1][3], o1); \
    MUL2(tmp, a2, s[4]); FMA2(s[4], c2, K[(I)][4], tmp); FMA2(o0, s[4], Q[(I) & 1][4], o0); \
    MUL2(tmp, a2, s[5]); FMA2(s[5], c2, K[(I)][5], tmp); FMA2(o1, s[5], Q[(I) & 1][5], o1); \
    MUL2(tmp, a2, s[6]); FMA2(s[6], c2, K[(I)][6], tmp); FMA2(o0, s[6], Q[(I) & 1][6], o0); \
    MUL2(tmp, a2, s[7]); FMA2(s[7], c2, K[(I)][7], tmp); FMA2(o1, s[7], Q[(I) & 1][7], o1); \
    float ox, oy, px, py; UNPK2(ox, oy, o0); UNPK2(px, py, o1); \
    float oo = redq((ox + px) + (oy + py)); \
    if (qu == 0) out[(size_t)(tt) * 8192 + ob] = oo; \
    if ((tt) + 8 < TT) LK((I), (tt) + 8); \
    if ((tt) + 2 < TT) LQ((I) & 1, (tt) + 2); \
    if ((tt) + 4 < TT) LV((I) & 3, (tt) + 4); }

__global__ __launch_bounds__(128, 1)
void scan(const float* __restrict__ S0, float* __restrict__ out)
{
    __shared__ float4 smkk[1024];

    const int blk = blockIdx.x;
    const int bh = blk >> 1;
    const int half = blk & 1;
    const int b = bh >> 4, h = bh & 15;
    const int tid = threadIdx.x;
    const int d = half * 32 + (tid >> 2);   // global row 0..63
    const int qu = tid & 3;

    const size_t base = (size_t)b * DD + h * 64;
    const float* qb = g_proj + base;
    const float* kb = g_proj + (size_t)SEGC + base;
    const float* vb = g_proj + 2ull * SEGC + base + d;
    const size_t ob = base + d;

    // ---- build kk table (lags 1..4 of normalized k) in smem ----
    {
        const int tq = tid >> 2;   // 0..31
        for (int tile = 0; tile < 32; tile++) {
            const int t = tile * 32 + tq;
            ull kt[8];
            ld16(kt, kb + (size_t)t * 8192 + qu * 16);
            float res[4];
#pragma unroll
            for (int j = 1; j <= 4; j++) {
                int tj = t + j; if (tj > 1023) tj = 1023;
                ull kj[8];
                ld16(kj, kb + (size_t)tj * 8192 + qu * 16);
                res[j - 1] = redq(dot16(kt, kj));
            }
            if (qu == 0) smkk[t] = make_float4(res[0], res[1], res[2], res[3]);
        }
    }
    __syncthreads();

    // ---- state ----
    ull s[8];
    ld16(s, S0 + ((size_t)bh * 64 + d) * 64 + qu * 16);

    // ---- rings ----
    ull K[8][8], Q[2][8];
    float va[4], aa[4], bba[4];
#pragma unroll
    for (int i = 0; i < 8; i++) LK(i, i);
    LQ(0, 0); LQ(1, 1);
    LV(0, 0); LV(1, 1); LV(2, 2); LV(3, 3);

    // ---- prologue dots ----
    float P0 = redq(dot16(s, K[0]));
    float P1 = redq(dot16(s, K[1]));
    float P2 = redq(dot16(s, K[2]));
    float ddrp = redq(dot16(s, K[3]));
    float ap = 1.0f, coefp = 0.0f, kk4p = 0.0f;
    float4 kknxt = smkk[0];

    for (int tb = 0; tb < TT; tb += 8) {
        STEP(0, tb);
        STEP(1, tb + 1);
        STEP(2, tb + 2);
        STEP(3, tb + 3);
        STEP(4, tb + 4);
        STEP(5, tb + 5);
        STEP(6, tb + 6);
        STEP(7, tb + 7);
    }

    // final state -> d_out tail region (B,H,DH,DH)
    {
        ulonglong2* So = (ulonglong2*)(out + (size_t)(TT * BB * DD) + ((size_t)bh * 64 + d) * 64 + qu * 16);
        So[0] = make_ulonglong2(s[0], s[1]);
        So[1] = make_ulonglong2(s[2], s[3]);
        So[2] = make_ulonglong2(s[4], s[5]);
        So[3] = make_ulonglong2(s[6], s[7]);
    }
}

// =====================================================================
extern "C" void kernel_launch(void* const* d_in, const int* in_sizes, int n_in,
                              void* d_out, int out_size)
{
    const float* x  = (const float*)d_in[0];
    const float* S0 = (const float*)d_in[1];
    const float* Wq = (const float*)d_in[2];
    const float* Wk = (const float*)d_in[3];
    const float* Wv = (const float*)d_in[4];
    const float* Wa = (const float*)d_in[5];
    const float* ba = (const float*)d_in[6];
    const float* Wb = (const float*)d_in[7];
    const float* bb = (const float*)d_in[8];
    float* out = (float*)d_out;

    cudaFuncSetAttribute(gemm_mma, cudaFuncAttributeMaxDynamicSharedMemorySize, 4 * STG);

    pack_all<<<6656, 256>>>(x, Wq, Wk, Wv, Wa, Wb);
    gemm_mma<<<2560, 256, 4 * STG>>>();
    postproc<<<16384, 256>>>(ba, bb);
    scan<<<256, 128>>>(S0, out);       // 4th launch -> ncu capture slot
}

// round 16
// speedup vs baseline: 1.2396x; 1.2396x over previous
#include <cuda_runtime.h>
#include <cuda_bf16.h>
#include <cstdint>

// ---------------- problem dims ----------------
#define TT 1024
#define BB 8
#define DD 1024
#define HH 16
#define ROWS 8192
#define SEGC 8388608u
#define KC 3072                 // concatenated split-bf16 K (hi|hi|lo vs hi|lo|hi)

typedef unsigned long long ull;

// ---------------- device scratch ----------------
__device__ float g_proj[5ull * SEGC];     // q,k,v (fp32; segs 3,4 unused now)
__device__ float g_alpha[ROWS * HH];
__device__ float g_beta[ROWS * HH];
__device__ __align__(16) __nv_bfloat16 g_xcat[(size_t)ROWS * KC];   // 48 MB
__device__ __align__(16) __nv_bfloat16 g_wcat[(size_t)5120 * KC];   // 30 MB

// ---------------- helpers ----------------
__device__ __forceinline__ uint32_t smem_u32(const void* p) {
    uint32_t a;
    asm("{ .reg .u64 t; cvta.to.shared.u64 t, %1; cvt.u32.u64 %0, t; }" : "=r"(a) : "l"(p));
    return a;
}
__device__ __forceinline__ void cpa16(uint32_t dst, const void* src) {
    asm volatile("cp.async.cg.shared.global [%0], [%1], 16;" :: "r"(dst), "l"(src));
}
#define CP_COMMIT() asm volatile("cp.async.commit_group;")
#define CP_WAIT2()  asm volatile("cp.async.wait_group 2;")

__device__ __forceinline__ void ldm4(uint32_t* r, uint32_t a) {
    asm volatile("ldmatrix.sync.aligned.m8n8.x4.shared.b16 {%0,%1,%2,%3}, [%4];"
        : "=r"(r[0]), "=r"(r[1]), "=r"(r[2]), "=r"(r[3]) : "r"(a));
}
__device__ __forceinline__ void mma16816(float* d, const uint32_t* a, uint32_t b0, uint32_t b1) {
    asm volatile(
        "mma.sync.aligned.m16n8k16.row.col.f32.bf16.bf16.f32 "
        "{%0,%1,%2,%3},{%4,%5,%6,%7},{%8,%9},{%0,%1,%2,%3};"
        : "+f"(d[0]), "+f"(d[1]), "+f"(d[2]), "+f"(d[3])
        : "r"(a[0]), "r"(a[1]), "r"(a[2]), "r"(a[3]), "r"(b0), "r"(b1));
}

// packed f32x2 (sm_100+ FFMA2)
#define FMA2(d, a, b, c) asm("fma.rn.f32x2 %0, %1, %2, %3;" : "=l"(d) : "l"(a), "l"(b), "l"(c))
#define MUL2(d, a, b)    asm("mul.rn.f32x2 %0, %1, %2;"     : "=l"(d) : "l"(a), "l"(b))
#define PK2(d, x, y)     asm("mov.b64 %0, {%1, %2};"        : "=l"(d) : "f"(x), "f"(y))
#define UNPK2(x, y, d)   asm("mov.b64 {%0, %1}, %2;"        : "=f"(x), "=f"(y) : "l"(d))

// split one float into bf16 hi + bf16 lo
__device__ __forceinline__ void split2(float f0, float f1, uint32_t& hw, uint32_t& lw) {
    __nv_bfloat16 h0 = __float2bfloat16(f0);
    __nv_bfloat16 h1 = __float2bfloat16(f1);
    __nv_bfloat16 l0 = __float2bfloat16(f0 - __bfloat162float(h0));
    __nv_bfloat16 l1 = __float2bfloat16(f1 - __bfloat162float(h1));
    hw = (uint32_t)__bfloat16_as_ushort(h0) | ((uint32_t)__bfloat16_as_ushort(h1) << 16);
    lw = (uint32_t)__bfloat16_as_ushort(l0) | ((uint32_t)__bfloat16_as_ushort(l1) << 16);
}

__device__ __forceinline__ float sigf(float x) { return 1.0f / (1.0f + expf(-x)); }

// =====================================================================
// pack_all: fused pack_x + pack_w (unchanged).
// =====================================================================
__global__ __launch_bounds__(256)
void pack_all(const float* __restrict__ x,
              const float* __restrict__ W0, const float* __restrict__ W1,
              const float* __restrict__ W2, const float* __restrict__ W3,
              const float* __restrict__ W4)
{
    unsigned idx = blockIdx.x * 256 + threadIdx.x;
    if (idx < 1048576u) {
        unsigned e = idx * 8;
        unsigned row = e >> 10, col = e & 1023;
        float4 f0 = *(const float4*)(x + e);
        float4 f1 = *(const float4*)(x + e + 4);
        uint4 hi, lo;
        split2(f0.x, f0.y, hi.x, lo.x);
        split2(f0.z, f0.w, hi.y, lo.y);
        split2(f1.x, f1.y, hi.z, lo.z);
        split2(f1.z, f1.w, hi.w, lo.w);
        __nv_bfloat16* base = g_xcat + (size_t)row * KC;
        *(uint4*)(base + col)        = hi;
        *(uint4*)(base + col + 1024) = hi;
        *(uint4*)(base + col + 2048) = lo;
    } else {
        unsigned j = idx - 1048576u;
        unsigned e = j * 8;
        unsigned seg = e >> 20;
        unsigned n = (e >> 10) & 1023, k = e & 1023;
        const float* W = (seg == 0) ? W0 : (seg == 1) ? W1 : (seg == 2) ? W2
                         : (seg == 3) ? W3 : W4;
        const float* src = W + (size_t)n * 1024 + k;
        float4 f0 = *(const float4*)(src);
        float4 f1 = *(const float4*)(src + 4);
        uint4 hi, lo;
        split2(f0.x, f0.y, hi.x, lo.x);
        split2(f0.z, f0.w, hi.y, lo.y);
        split2(f1.x, f1.y, hi.z, lo.z);
        split2(f1.z, f1.w, hi.w, lo.w);
        __nv_bfloat16* base = g_wcat + (size_t)(seg * 1024 + n) * KC;
        *(uint4*)(base + k)        = hi;
        *(uint4*)(base + k + 1024) = lo;
        *(uint4*)(base + k + 2048) = hi;
    }
}

// =====================================================================
// gemm_mma: R8 mainloop (best measured: 752.9us, tensor 56.6%) +
// FUSED postproc epilogue:
//   seg 0/1 (q,k): per-head (64-col) l2norm inside the CTA, scaled store
//   seg 2   (v)  : plain store
//   seg 3/4 (a,b): sigmoid(x+bias) head-mean -> g_alpha/g_beta only
//                  (no 128x128 tile store at all)
// Head reduction: thread 8-col sums -> shfl_xor 1,2 -> smem strip table
// (reuses the mainloop stage ring) -> pair-combine.
// =====================================================================
#define STG 20480

__global__ __launch_bounds__(256, 2)
void gemm_mma(const float* __restrict__ ba, const float* __restrict__ bb)
{
    extern __shared__ __align__(16) unsigned char sm[];
    const uint32_t smb = smem_u32(sm);

    const int bid = blockIdx.x;
    const int mt = bid / 40, nt = bid % 40;
    const int tid = threadIdx.x;
    const int lane = tid & 31, wid = tid >> 5;
    const int wm = wid & 1, wn = wid >> 1;

    const int lrow = tid >> 2, lch = tid & 3;
    const __nv_bfloat16* Ag = g_xcat + (size_t)(mt * 128 + lrow) * KC + lch * 8;
    const __nv_bfloat16* Bg = g_wcat + (size_t)(nt * 128 + lrow) * KC + lch * 8;
    const uint32_t sA = smb + lrow * 80 + lch * 16;
    const uint32_t sB = smb + 10240 + lrow * 80 + lch * 16;

    auto load = [&](int it, int stage) {
        const uint32_t off = stage * STG;
        const __nv_bfloat16* ag = Ag + it * 32;
        const __nv_bfloat16* bg = Bg + it * 32;
        cpa16(sA + off,           ag);
        cpa16(sA + off + 64 * 80, ag + (size_t)64 * KC);
        cpa16(sB + off,           bg);
        cpa16(sB + off + 64 * 80, bg + (size_t)64 * KC);
    };

    uint32_t aAddr[4], bAddr[2];
#pragma unroll
    for (int f = 0; f < 4; f++)
        aAddr[f] = smb + (wm * 64 + f * 16 + (lane & 15)) * 80 + (lane >> 4) * 16;
#pragma unroll
    for (int x = 0; x < 2; x++)
        bAddr[x] = smb + 10240 + (wn * 32 + x * 16 + (lane & 15)) * 80 + (lane >> 4) * 16;

    float acc[4][4][4];
#pragma unroll
    for (int f = 0; f < 4; f++)
#pragma unroll
        for (int g = 0; g < 4; g++)
#pragma unroll
            for (int i = 0; i < 4; i++) acc[f][g][i] = 0.f;

    load(0, 0); CP_COMMIT();
    load(1, 1); CP_COMMIT();
    load(2, 2); CP_COMMIT();

    const int NIT = KC / 32;    // 96
    for (int it = 0; it < NIT; it++) {
        CP_WAIT2();
        __syncthreads();
        if (it + 3 < NIT) load(it + 3, (it + 3) & 3);
        CP_COMMIT();

        const uint32_t st = (it & 3) * STG;
#pragma unroll
        for (int ks = 0; ks < 2; ks++) {
            uint32_t af[4][4], bf[2][4];
#pragma unroll
            for (int f = 0; f < 4; f++) ldm4(af[f], aAddr[f] + st + ks * 32);
#pragma unroll
            for (int x = 0; x < 2; x++) ldm4(bf[x], bAddr[x] + st + ks * 32);
#pragma unroll
            for (int f = 0; f < 4; f++) {
#pragma unroll
                for (int g = 0; g < 4; g++) {
                    const uint32_t b0 = bf[g >> 1][g & 1];
                    const uint32_t b1 = bf[g >> 1][(g & 1) + 2];
                    mma16816(acc[f][g], af[f], b0, b1);
                }
            }
        }
    }

    // ---------------- fused epilogue ----------------
    __syncthreads();                   // smem ring dead; reuse as reduction table
    float* red = (float*)sm;           // [128 rows][4 strips]

    const int seg = nt >> 3;
    const int rl0 = wm * 64 + (lane >> 2);              // local row base
    const int cIn = wn * 32 + (lane & 3) * 2;           // col within 128-block
    // value (f, g, i): local row rl0 + f*16 + (i>>1)*8, col cIn + g*8 + (i&1)

    if (seg == 2) {
        // v: plain store (unchanged layout)
        float* op = g_proj + 2ull * SEGC;
        const int rbase = mt * 128 + rl0;
        const int cbase = (nt & 7) * 128 + cIn;
#pragma unroll
        for (int f = 0; f < 4; f++) {
#pragma unroll
            for (int g = 0; g < 4; g++) {
                const int r = rbase + f * 16;
                const int c = cbase + g * 8;
                float2 v0 = make_float2(acc[f][g][0], acc[f][g][1]);
                float2 v1 = make_float2(acc[f][g][2], acc[f][g][3]);
                *(float2*)(op + (size_t)r * 1024 + c)       = v0;
                *(float2*)(op + (size_t)(r + 8) * 1024 + c) = v1;
            }
        }
    } else if (seg <= 1) {
        // q/k: per-head l2norm then scaled store
        float ss[4][2];
#pragma unroll
        for (int f = 0; f < 4; f++) {
#pragma unroll
            for (int hv = 0; hv < 2; hv++) {
                float s = 0.f;
#pragma unroll
                for (int g = 0; g < 4; g++) {
                    const float v0 = acc[f][g][hv * 2], v1 = acc[f][g][hv * 2 + 1];
                    s = fmaf(v0, v0, s);
                    s = fmaf(v1, v1, s);
                }
                s += __shfl_xor_sync(0xffffffffu, s, 1);
                s += __shfl_xor_sync(0xffffffffu, s, 2);
                ss[f][hv] = s;
            }
        }
        if ((lane & 3) == 0) {
#pragma unroll
            for (int f = 0; f < 4; f++)
#pragma unroll
                for (int hv = 0; hv < 2; hv++)
                    red[(rl0 + f * 16 + hv * 8) * 4 + wn] = ss[f][hv];
        }
        __syncthreads();
        float* op = g_proj + (size_t)seg * SEGC;
        const int wn0 = wn & ~1;
        const int cbase = (nt & 7) * 128 + cIn;
#pragma unroll
        for (int f = 0; f < 4; f++) {
#pragma unroll
            for (int hv = 0; hv < 2; hv++) {
                const int rl = rl0 + f * 16 + hv * 8;
                const float tot = red[rl * 4 + wn0] + red[rl * 4 + wn0 + 1];
                const float scale = 1.0f / fmaxf(sqrtf(tot), 1e-12f);
                const int r = mt * 128 + rl;
#pragma unroll
                for (int g = 0; g < 4; g++) {
                    float2 v = make_float2(acc[f][g][hv * 2] * scale,
                                           acc[f][g][hv * 2 + 1] * scale);
                    *(float2*)(op + (size_t)r * 1024 + cbase + g * 8) = v;
                }
            }
        }
    } else {
        // alpha/beta: sigmoid(val + bias) head-mean -> g_alpha/g_beta
        const float* bias = (seg == 3) ? ba : bb;
        const int cb = (nt & 7) * 128 + cIn;
        float bv0[4], bv1[4];
#pragma unroll
        for (int g = 0; g < 4; g++) {
            bv0[g] = bias[cb + g * 8];
            bv1[g] = bias[cb + g * 8 + 1];
        }
        float ss[4][2];
#pragma unroll
        for (int f = 0; f < 4; f++) {
#pragma unroll
            for (int hv = 0; hv < 2; hv++) {
                float s = 0.f;
#pragma unroll
                for (int g = 0; g < 4; g++) {
                    s += sigf(acc[f][g][hv * 2]     + bv0[g]);
                    s += sigf(acc[f][g][hv * 2 + 1] + bv1[g]);
                }
                s += __shfl_xor_sync(0xffffffffu, s, 1);
                s += __shfl_xor_sync(0xffffffffu, s, 2);
                ss[f][hv] = s;
            }
        }
        if ((lane & 3) == 0) {
#pragma unroll
            for (int f = 0; f < 4; f++)
#pragma unroll
                for (int hv = 0; hv < 2; hv++)
                    red[(rl0 + f * 16 + hv * 8) * 4 + wn] = ss[f][hv];
        }
        __syncthreads();
        if ((lane & 3) == 0 && !(wn & 1)) {
            float* dst = (seg == 3) ? g_alpha : g_beta;
            const int headg = (nt & 7) * 2 + (wn >> 1);
#pragma unroll
            for (int f = 0; f < 4; f++) {
#pragma unroll
                for (int hv = 0; hv < 2; hv++) {
                    const int rl = rl0 + f * 16 + hv * 8;
                    const float tot = red[rl * 4 + wn] + red[rl * 4 + wn + 1];
                    dst[(size_t)(mt * 128 + rl) * 16 + headg] = tot * 0.015625f;
                }
            }
        }
    }
}

// =====================================================================
// scan: EXACT R13 v6 (best measured 334.7us).
// grid = 256 (bh x half), block = 128 (32 rows x 4 col-quarters).
// =====================================================================
#define LOADS(S, t) { \
    const float4* kp = (const float4*)(kb + (size_t)(t) * 8192) + (qu * 4); \
    kr##S##_0 = kp[0]; kr##S##_1 = kp[1]; kr##S##_2 = kp[2]; kr##S##_3 = kp[3]; \
    const float4* qp = (const float4*)(qb + (size_t)(t) * 8192) + (qu * 4); \
    qr##S##_0 = qp[0]; qr##S##_1 = qp[1]; qr##S##_2 = qp[2]; qr##S##_3 = qp[3]; \
    vr##S = vb[(size_t)(t) * 8192 + d]; \
    ar##S = g_alpha[(t) * 128 + bh]; \
    br##S = g_beta[(t) * 128 + bh]; }

#define STEP(S, tt) { \
    const float a = ar##S, be = br##S, vv = vr##S; \
    ull K0,K1,K2,K3,K4,K5,K6,K7, Q0,Q1,Q2,Q3,Q4,Q5,Q6,Q7; \
    PK2(K0, kr##S##_0.x, kr##S##_0.y); PK2(K1, kr##S##_0.z, kr##S##_0.w); \
    PK2(K2, kr##S##_1.x, kr##S##_1.y); PK2(K3, kr##S##_1.z, kr##S##_1.w); \
    PK2(K4, kr##S##_2.x, kr##S##_2.y); PK2(K5, kr##S##_2.z, kr##S##_2.w); \
    PK2(K6, kr##S##_3.x, kr##S##_3.y); PK2(K7, kr##S##_3.z, kr##S##_3.w); \
    PK2(Q0, qr##S##_0.x, qr##S##_0.y); PK2(Q1, qr##S##_0.z, qr##S##_0.w); \
    PK2(Q2, qr##S##_1.x, qr##S##_1.y); PK2(Q3, qr##S##_1.z, qr##S##_1.w); \
    PK2(Q4, qr##S##_2.x, qr##S##_2.y); PK2(Q5, qr##S##_2.z, qr##S##_2.w); \
    PK2(Q6, qr##S##_3.x, qr##S##_3.y); PK2(Q7, qr##S##_3.z, qr##S##_3.w); \
    ull d0, d1; \
    MUL2(d0, s_0, K0); MUL2(d1, s_1, K1); \
    FMA2(d0, s_2, K2, d0); FMA2(d1, s_3, K3, d1); \
    FMA2(d0, s_4, K4, d0); FMA2(d1, s_5, K5, d1); \
    FMA2(d0, s_6, K6, d0); FMA2(d1, s_7, K7, d1); \
    float dx, dy, ex, ey; UNPK2(dx, dy, d0); UNPK2(ex, ey, d1); \
    float sk = (dx + ex) + (dy + ey); \
    sk += __shfl_xor_sync(0xffffffffu, sk, 1); \
    sk += __shfl_xor_sync(0xffffffffu, sk, 2); \
    const float coef = be * fmaf(-a, sk, vv); \
    ull a2, c2; PK2(a2, a, a); PK2(c2, coef, coef); \
    ull o0, o1, tmp; \
    MUL2(tmp, a2, s_0); FMA2(s_0, c2, K0, tmp); MUL2(o0, s_0, Q0); \
    MUL2(tmp, a2, s_1); FMA2(s_1, c2, K1, tmp); MUL2(o1, s_1, Q1); \
    MUL2(tmp, a2, s_2); FMA2(s_2, c2, K2, tmp); FMA2(o0, s_2, Q2, o0); \
    MUL2(tmp, a2, s_3); FMA2(s_3, c2, K3, tmp); FMA2(o1, s_3, Q3, o1); \
    MUL2(tmp, a2, s_4); FMA2(s_4, c2, K4, tmp); FMA2(o0, s_4, Q4, o0); \
    MUL2(tmp, a2, s_5); FMA2(s_5, c2, K5, tmp); FMA2(o1, s_5, Q5, o1); \
    MUL2(tmp, a2, s_6); FMA2(s_6, c2, K6, tmp); FMA2(o0, s_6, Q6, o0); \
    MUL2(tmp, a2, s_7); FMA2(s_7, c2, K7, tmp); FMA2(o1, s_7, Q7, o1); \
    float ox, oy, px, py; UNPK2(ox, oy, o0); UNPK2(px, py, o1); \
    float oo = (ox + px) + (oy + py); \
    oo += __shfl_xor_sync(0xffffffffu, oo, 1); \
    oo += __shfl_xor_sync(0xffffffffu, oo, 2); \
    if (qu == 0) out[(size_t)(tt) * 8192 + ob] = oo; \
    if ((tt) + 4 < TT) LOADS(S, (tt) + 4); }

__global__ __launch_bounds__(128, 1)
void scan(const float* __restrict__ S0, float* __restrict__ out)
{
    const int blk = blockIdx.x;
    const int bh = blk >> 1;               // (b,h) chain
    const int half = blk & 1;              // row half: [0,32) or [32,64)
    const int b = bh >> 4, h = bh & 15;
    const int tid = threadIdx.x;
    const int d = half * 32 + (tid >> 2);  // global row 0..63
    const int qu = tid & 3;

    const float4* Sp = (const float4*)(S0 + ((size_t)bh * 64 + d) * 64 + qu * 16);
    float4 i0 = Sp[0], i1 = Sp[1], i2 = Sp[2], i3 = Sp[3];
    ull s_0, s_1, s_2, s_3, s_4, s_5, s_6, s_7;
    PK2(s_0, i0.x, i0.y); PK2(s_1, i0.z, i0.w);
    PK2(s_2, i1.x, i1.y); PK2(s_3, i1.z, i1.w);
    PK2(s_4, i2.x, i2.y); PK2(s_5, i2.z, i2.w);
    PK2(s_6, i3.x, i3.y); PK2(s_7, i3.z, i3.w);

    const size_t base = (size_t)b * DD + h * 64;
    const float* qb = g_proj + base;
    const float* kb = g_proj + (size_t)SEGC + base;
    const float* vb = g_proj + 2ull * SEGC + base;
    const size_t ob = (size_t)b * DD + h * 64 + d;

    float4 kr0_0, kr0_1, kr0_2, kr0_3, qr0_0, qr0_1, qr0_2, qr0_3;
    float4 kr1_0, kr1_1, kr1_2, kr1_3, qr1_0, qr1_1, qr1_2, qr1_3;
    float4 kr2_0, kr2_1, kr2_2, kr2_3, qr2_0, qr2_1, qr2_2, qr2_3;
    float4 kr3_0, kr3_1, kr3_2, kr3_3, qr3_0, qr3_1, qr3_2, qr3_3;
    float vr0, ar0, br0, vr1, ar1, br1, vr2, ar2, br2, vr3, ar3, br3;

    LOADS(0, 0); LOADS(1, 1); LOADS(2, 2); LOADS(3, 3);

    for (int t = 0; t < TT; t += 4) {
        STEP(0, t);
        STEP(1, t + 1);
        STEP(2, t + 2);
        STEP(3, t + 3);
    }

    float4 f0, f1, f2, f3;
    UNPK2(f0.x, f0.y, s_0); UNPK2(f0.z, f0.w, s_1);
    UNPK2(f1.x, f1.y, s_2); UNPK2(f1.z, f1.w, s_3);
    UNPK2(f2.x, f2.y, s_4); UNPK2(f2.z, f2.w, s_5);
    UNPK2(f3.x, f3.y, s_6); UNPK2(f3.z, f3.w, s_7);
    float4* So = (float4*)(out + (size_t)(TT * BB * DD) + ((size_t)bh * 64 + d) * 64 + qu * 16);
    So[0] = f0; So[1] = f1; So[2] = f2; So[3] = f3;
}

// =====================================================================
extern "C" void kernel_launch(void* const* d_in, const int* in_sizes, int n_in,
                              void* d_out, int out_size)
{
    const float* x  = (const float*)d_in[0];
    const float* S0 = (const float*)d_in[1];
    const float* Wq = (const float*)d_in[2];
    const float* Wk = (const float*)d_in[3];
    const float* Wv = (const float*)d_in[4];
    const float* Wa = (const float*)d_in[5];
    const float* ba = (const float*)d_in[6];
    const float* Wb = (const float*)d_in[7];
    const float* bb = (const float*)d_in[8];
    float* out = (float*)d_out;

    cudaFuncSetAttribute(gemm_mma, cudaFuncAttributeMaxDynamicSharedMemorySize, 4 * STG);

    pack_all<<<6656, 256>>>(x, Wq, Wk, Wv, Wa, Wb);
    gemm_mma<<<2560, 256, 4 * STG>>>(ba, bb);
    scan<<<256, 128>>>(S0, out);
}

// round 17
// speedup vs baseline: 1.5856x; 1.2791x over previous
#include <cuda_runtime.h>
#include <cuda_bf16.h>
#include <cuda_fp16.h>
#include <cstdint>

// ---------------- problem dims ----------------
#define TT 1024
#define BB 8
#define DD 1024
#define HH 16
#define ROWS 8192
#define SEGC 8388608u
#define KC 2048                 // fp16 2-term split: X=[hi|lo], W=[hi|hi]

typedef unsigned long long ull;

// ---------------- device scratch ----------------
__device__ float g_proj[5ull * SEGC];     // q,k,v (segs 3,4 unused)
__device__ float g_alpha[ROWS * HH];
__device__ float g_beta[ROWS * HH];
__device__ __align__(16) __half g_xcat[(size_t)ROWS * KC];   // 32 MB
__device__ __align__(16) __half g_wcat[(size_t)5120 * KC];   // 20 MB

// ---------------- helpers ----------------
__device__ __forceinline__ uint32_t smem_u32(const void* p) {
    uint32_t a;
    asm("{ .reg .u64 t; cvta.to.shared.u64 t, %1; cvt.u32.u64 %0, t; }" : "=r"(a) : "l"(p));
    return a;
}
__device__ __forceinline__ void cpa16(uint32_t dst, const void* src) {
    asm volatile("cp.async.cg.shared.global [%0], [%1], 16;" :: "r"(dst), "l"(src));
}
#define CP_COMMIT() asm volatile("cp.async.commit_group;")
#define CP_WAIT2()  asm volatile("cp.async.wait_group 2;")

__device__ __forceinline__ void ldm4(uint32_t* r, uint32_t a) {
    asm volatile("ldmatrix.sync.aligned.m8n8.x4.shared.b16 {%0,%1,%2,%3}, [%4];"
        : "=r"(r[0]), "=r"(r[1]), "=r"(r[2]), "=r"(r[3]) : "r"(a));
}
__device__ __forceinline__ void mma16816(float* d, const uint32_t* a, uint32_t b0, uint32_t b1) {
    asm volatile(
        "mma.sync.aligned.m16n8k16.row.col.f32.f16.f16.f32 "
        "{%0,%1,%2,%3},{%4,%5,%6,%7},{%8,%9},{%0,%1,%2,%3};"
        : "+f"(d[0]), "+f"(d[1]), "+f"(d[2]), "+f"(d[3])
        : "r"(a[0]), "r"(a[1]), "r"(a[2]), "r"(a[3]), "r"(b0), "r"(b1));
}

// packed f32x2 (sm_100+ FFMA2)
#define FMA2(d, a, b, c) asm("fma.rn.f32x2 %0, %1, %2, %3;" : "=l"(d) : "l"(a), "l"(b), "l"(c))
#define MUL2(d, a, b)    asm("mul.rn.f32x2 %0, %1, %2;"     : "=l"(d) : "l"(a), "l"(b))
#define PK2(d, x, y)     asm("mov.b64 %0, {%1, %2};"        : "=l"(d) : "f"(x), "f"(y))
#define UNPK2(x, y, d)   asm("mov.b64 {%0, %1}, %2;"        : "=f"(x), "=f"(y) : "l"(d))

// split one float pair into fp16 hi + fp16 lo (packed half2 words)
__device__ __forceinline__ void split2h(float f0, float f1, uint32_t& hw, uint32_t& lw) {
    __half h0 = __float2half_rn(f0);
    __half h1 = __float2half_rn(f1);
    __half l0 = __float2half_rn(f0 - __half2float(h0));
    __half l1 = __float2half_rn(f1 - __half2float(h1));
    hw = (uint32_t)__half_as_ushort(h0) | ((uint32_t)__half_as_ushort(h1) << 16);
    lw = (uint32_t)__half_as_ushort(l0) | ((uint32_t)__half_as_ushort(l1) << 16);
}

__device__ __forceinline__ float sigf(float x) { return 1.0f / (1.0f + expf(-x)); }

// =====================================================================
// pack_all: X (8192,1024) fp32 -> Xcat (8192,2048) f16 = [hi | lo]
//           W stack (5120,1024) fp32 -> Wcat (5120,2048) f16 = [hi | hi]
// =====================================================================
__global__ __launch_bounds__(256)
void pack_all(const float* __restrict__ x,
              const float* __restrict__ W0, const float* __restrict__ W1,
              const float* __restrict__ W2, const float* __restrict__ W3,
              const float* __restrict__ W4)
{
    unsigned idx = blockIdx.x * 256 + threadIdx.x;
    if (idx < 1048576u) {
        unsigned e = idx * 8;
        unsigned row = e >> 10, col = e & 1023;
        float4 f0 = *(const float4*)(x + e);
        float4 f1 = *(const float4*)(x + e + 4);
        uint4 hi, lo;
        split2h(f0.x, f0.y, hi.x, lo.x);
        split2h(f0.z, f0.w, hi.y, lo.y);
        split2h(f1.x, f1.y, hi.z, lo.z);
        split2h(f1.z, f1.w, hi.w, lo.w);
        __half* base = g_xcat + (size_t)row * KC;
        *(uint4*)(base + col)        = hi;
        *(uint4*)(base + col + 1024) = lo;
    } else {
        unsigned j = idx - 1048576u;
        unsigned e = j * 8;
        unsigned seg = e >> 20;
        unsigned n = (e >> 10) & 1023, k = e & 1023;
        const float* W = (seg == 0) ? W0 : (seg == 1) ? W1 : (seg == 2) ? W2
                         : (seg == 3) ? W3 : W4;
        const float* src = W + (size_t)n * 1024 + k;
        float4 f0 = *(const float4*)(src);
        float4 f1 = *(const float4*)(src + 4);
        uint4 hi, lo;
        split2h(f0.x, f0.y, hi.x, lo.x);
        split2h(f0.z, f0.w, hi.y, lo.y);
        split2h(f1.x, f1.y, hi.z, lo.z);
        split2h(f1.z, f1.w, hi.w, lo.w);
        __half* base = g_wcat + (size_t)(seg * 1024 + n) * KC;
        *(uint4*)(base + k)        = hi;
        *(uint4*)(base + k + 1024) = hi;   // [hi | hi]
    }
}

// =====================================================================
// gemm_mma: R8 mainloop shape (BM=BN=128, BK=32, 4-stage ring, 8 warps,
// warp tile 64x32, 2 CTAs/SM), now fp16 2-term (KC=2048, NIT=64) +
// R16 fused postproc epilogue.
// =====================================================================
#define STG 20480

__global__ __launch_bounds__(256, 2)
void gemm_mma(const float* __restrict__ ba, const float* __restrict__ bb)
{
    extern __shared__ __align__(16) unsigned char sm[];
    const uint32_t smb = smem_u32(sm);

    const int bid = blockIdx.x;
    const int mt = bid / 40, nt = bid % 40;
    const int tid = threadIdx.x;
    const int lane = tid & 31, wid = tid >> 5;
    const int wm = wid & 1, wn = wid >> 1;

    const int lrow = tid >> 2, lch = tid & 3;
    const __half* Ag = g_xcat + (size_t)(mt * 128 + lrow) * KC + lch * 8;
    const __half* Bg = g_wcat + (size_t)(nt * 128 + lrow) * KC + lch * 8;
    const uint32_t sA = smb + lrow * 80 + lch * 16;
    const uint32_t sB = smb + 10240 + lrow * 80 + lch * 16;

    auto load = [&](int it, int stage) {
        const uint32_t off = stage * STG;
        const __half* ag = Ag + it * 32;
        const __half* bg = Bg + it * 32;
        cpa16(sA + off,           ag);
        cpa16(sA + off + 64 * 80, ag + (size_t)64 * KC);
        cpa16(sB + off,           bg);
        cpa16(sB + off + 64 * 80, bg + (size_t)64 * KC);
    };

    uint32_t aAddr[4], bAddr[2];
#pragma unroll
    for (int f = 0; f < 4; f++)
        aAddr[f] = smb + (wm * 64 + f * 16 + (lane & 15)) * 80 + (lane >> 4) * 16;
#pragma unroll
    for (int x = 0; x < 2; x++)
        bAddr[x] = smb + 10240 + (wn * 32 + x * 16 + (lane & 15)) * 80 + (lane >> 4) * 16;

    float acc[4][4][4];
#pragma unroll
    for (int f = 0; f < 4; f++)
#pragma unroll
        for (int g = 0; g < 4; g++)
#pragma unroll
            for (int i = 0; i < 4; i++) acc[f][g][i] = 0.f;

    load(0, 0); CP_COMMIT();
    load(1, 1); CP_COMMIT();
    load(2, 2); CP_COMMIT();

    const int NIT = KC / 32;    // 64
    for (int it = 0; it < NIT; it++) {
        CP_WAIT2();
        __syncthreads();
        if (it + 3 < NIT) load(it + 3, (it + 3) & 3);
        CP_COMMIT();

        const uint32_t st = (it & 3) * STG;
#pragma unroll
        for (int ks = 0; ks < 2; ks++) {
            uint32_t af[4][4], bf[2][4];
#pragma unroll
            for (int f = 0; f < 4; f++) ldm4(af[f], aAddr[f] + st + ks * 32);
#pragma unroll
            for (int x = 0; x < 2; x++) ldm4(bf[x], bAddr[x] + st + ks * 32);
#pragma unroll
            for (int f = 0; f < 4; f++) {
#pragma unroll
                for (int g = 0; g < 4; g++) {
                    const uint32_t b0 = bf[g >> 1][g & 1];
                    const uint32_t b1 = bf[g >> 1][(g & 1) + 2];
                    mma16816(acc[f][g], af[f], b0, b1);
                }
            }
        }
    }

    // ---------------- fused epilogue (R16, unchanged) ----------------
    __syncthreads();
    float* red = (float*)sm;

    const int seg = nt >> 3;
    const int rl0 = wm * 64 + (lane >> 2);
    const int cIn = wn * 32 + (lane & 3) * 2;

    if (seg == 2) {
        float* op = g_proj + 2ull * SEGC;
        const int rbase = mt * 128 + rl0;
        const int cbase = (nt & 7) * 128 + cIn;
#pragma unroll
        for (int f = 0; f < 4; f++) {
#pragma unroll
            for (int g = 0; g < 4; g++) {
                const int r = rbase + f * 16;
                const int c = cbase + g * 8;
                float2 v0 = make_float2(acc[f][g][0], acc[f][g][1]);
                float2 v1 = make_float2(acc[f][g][2], acc[f][g][3]);
                *(float2*)(op + (size_t)r * 1024 + c)       = v0;
                *(float2*)(op + (size_t)(r + 8) * 1024 + c) = v1;
            }
        }
    } else if (seg <= 1) {
        float ss[4][2];
#pragma unroll
        for (int f = 0; f < 4; f++) {
#pragma unroll
            for (int hv = 0; hv < 2; hv++) {
                float s = 0.f;
#pragma unroll
                for (int g = 0; g < 4; g++) {
                    const float v0 = acc[f][g][hv * 2], v1 = acc[f][g][hv * 2 + 1];
                    s = fmaf(v0, v0, s);
                    s = fmaf(v1, v1, s);
                }
                s += __shfl_xor_sync(0xffffffffu, s, 1);
                s += __shfl_xor_sync(0xffffffffu, s, 2);
                ss[f][hv] = s;
            }
        }
        if ((lane & 3) == 0) {
#pragma unroll
            for (int f = 0; f < 4; f++)
#pragma unroll
                for (int hv = 0; hv < 2; hv++)
                    red[(rl0 + f * 16 + hv * 8) * 4 + wn] = ss[f][hv];
        }
        __syncthreads();
        float* op = g_proj + (size_t)seg * SEGC;
        const int wn0 = wn & ~1;
        const int cbase = (nt & 7) * 128 + cIn;
#pragma unroll
        for (int f = 0; f < 4; f++) {
#pragma unroll
            for (int hv = 0; hv < 2; hv++) {
                const int rl = rl0 + f * 16 + hv * 8;
                const float tot = red[rl * 4 + wn0] + red[rl * 4 + wn0 + 1];
                const float scale = 1.0f / fmaxf(sqrtf(tot), 1e-12f);
                const int r = mt * 128 + rl;
#pragma unroll
                for (int g = 0; g < 4; g++) {
                    float2 v = make_float2(acc[f][g][hv * 2] * scale,
                                           acc[f][g][hv * 2 + 1] * scale);
                    *(float2*)(op + (size_t)r * 1024 + cbase + g * 8) = v;
                }
            }
        }
    } else {
        const float* bias = (seg == 3) ? ba : bb;
        const int cb = (nt & 7) * 128 + cIn;
        float bv0[4], bv1[4];
#pragma unroll
        for (int g = 0; g < 4; g++) {
            bv0[g] = bias[cb + g * 8];
            bv1[g] = bias[cb + g * 8 + 1];
        }
        float ss[4][2];
#pragma unroll
        for (int f = 0; f < 4; f++) {
#pragma unroll
            for (int hv = 0; hv < 2; hv++) {
                float s = 0.f;
#pragma unroll
                for (int g = 0; g < 4; g++) {
                    s += sigf(acc[f][g][hv * 2]     + bv0[g]);
                    s += sigf(acc[f][g][hv * 2 + 1] + bv1[g]);
                }
                s += __shfl_xor_sync(0xffffffffu, s, 1);
                s += __shfl_xor_sync(0xffffffffu, s, 2);
                ss[f][hv] = s;
            }
        }
        if ((lane & 3) == 0) {
#pragma unroll
            for (int f = 0; f < 4; f++)
#pragma unroll
                for (int hv = 0; hv < 2; hv++)
                    red[(rl0 + f * 16 + hv * 8) * 4 + wn] = ss[f][hv];
        }
        __syncthreads();
        if ((lane & 3) == 0 && !(wn & 1)) {
            float* dst = (seg == 3) ? g_alpha : g_beta;
            const int headg = (nt & 7) * 2 + (wn >> 1);
#pragma unroll
            for (int f = 0; f < 4; f++) {
#pragma unroll
                for (int hv = 0; hv < 2; hv++) {
                    const int rl = rl0 + f * 16 + hv * 8;
                    const float tot = red[rl * 4 + wn] + red[rl * 4 + wn + 1];
                    dst[(size_t)(mt * 128 + rl) * 16 + headg] = tot * 0.015625f;
                }
            }
        }
    }
}

// =====================================================================
// scan: EXACT R13 v6 (best measured 334.7us).
// =====================================================================
#define LOADS(S, t) { \
    const float4* kp = (const float4*)(kb + (size_t)(t) * 8192) + (qu * 4); \
    kr##S##_0 = kp[0]; kr##S##_1 = kp[1]; kr##S##_2 = kp[2]; kr##S##_3 = kp[3]; \
    const float4* qp = (const float4*)(qb + (size_t)(t) * 8192) + (qu * 4); \
    qr##S##_0 = qp[0]; qr##S##_1 = qp[1]; qr##S##_2 = qp[2]; qr##S##_3 = qp[3]; \
    vr##S = vb[(size_t)(t) * 8192 + d]; \
    ar##S = g_alpha[(t) * 128 + bh]; \
    br##S = g_beta[(t) * 128 + bh]; }

#define STEP(S, tt) { \
    const float a = ar##S, be = br##S, vv = vr##S; \
    ull K0,K1,K2,K3,K4,K5,K6,K7, Q0,Q1,Q2,Q3,Q4,Q5,Q6,Q7; \
    PK2(K0, kr##S##_0.x, kr##S##_0.y); PK2(K1, kr##S##_0.z, kr##S##_0.w); \
    PK2(K2, kr##S##_1.x, kr##S##_1.y); PK2(K3, kr##S##_1.z, kr##S##_1.w); \
    PK2(K4, kr##S##_2.x, kr##S##_2.y); PK2(K5, kr##S##_2.z, kr##S##_2.w); \
    PK2(K6, kr##S##_3.x, kr##S##_3.y); PK2(K7, kr##S##_3.z, kr##S##_3.w); \
    PK2(Q0, qr##S##_0.x, qr##S##_0.y); PK2(Q1, qr##S##_0.z, qr##S##_0.w); \
    PK2(Q2, qr##S##_1.x, qr##S##_1.y); PK2(Q3, qr##S##_1.z, qr##S##_1.w); \
    PK2(Q4, qr##S##_2.x, qr##S##_2.y); PK2(Q5, qr##S##_2.z, qr##S##_2.w); \
    PK2(Q6, qr##S##_3.x, qr##S##_3.y); PK2(Q7, qr##S##_3.z, qr##S##_3.w); \
    ull d0, d1; \
    MUL2(d0, s_0, K0); MUL2(d1, s_1, K1); \
    FMA2(d0, s_2, K2, d0); FMA2(d1, s_3, K3, d1); \
    FMA2(d0, s_4, K4, d0); FMA2(d1, s_5, K5, d1); \
    FMA2(d0, s_6, K6, d0); FMA2(d1, s_7, K7, d1); \
    float dx, dy, ex, ey; UNPK2(dx, dy, d0); UNPK2(ex, ey, d1); \
    float sk = (dx + ex) + (dy + ey); \
    sk += __shfl_xor_sync(0xffffffffu, sk, 1); \
    sk += __shfl_xor_sync(0xffffffffu, sk, 2); \
    const float coef = be * fmaf(-a, sk, vv); \
    ull a2, c2; PK2(a2, a, a); PK2(c2, coef, coef); \
    ull o0, o1, tmp; \
    MUL2(tmp, a2, s_0); FMA2(s_0, c2, K0, tmp); MUL2(o0, s_0, Q0); \
    MUL2(tmp, a2, s_1); FMA2(s_1, c2, K1, tmp); MUL2(o1, s_1, Q1); \
    MUL2(tmp, a2, s_2); FMA2(s_2, c2, K2, tmp); FMA2(o0, s_2, Q2, o0); \
    MUL2(tmp, a2, s_3); FMA2(s_3, c2, K3, tmp); FMA2(o1, s_3, Q3, o1); \
    MUL2(tmp, a2, s_4); FMA2(s_4, c2, K4, tmp); FMA2(o0, s_4, Q4, o0); \
    MUL2(tmp, a2, s_5); FMA2(s_5, c2, K5, tmp); FMA2(o1, s_5, Q5, o1); \
    MUL2(tmp, a2, s_6); FMA2(s_6, c2, K6, tmp); FMA2(o0, s_6, Q6, o0); \
    MUL2(tmp, a2, s_7); FMA2(s_7, c2, K7, tmp); FMA2(o1, s_7, Q7, o1); \
    float ox, oy, px, py; UNPK2(ox, oy, o0); UNPK2(px, py, o1); \
    float oo = (ox + px) + (oy + py); \
    oo += __shfl_xor_sync(0xffffffffu, oo, 1); \
    oo += __shfl_xor_sync(0xffffffffu, oo, 2); \
    if (qu == 0) out[(size_t)(tt) * 8192 + ob] = oo; \
    if ((tt) + 4 < TT) LOADS(S, (tt) + 4); }

__global__ __launch_bounds__(128, 1)
void scan(const float* __restrict__ S0, float* __restrict__ out)
{
    const int blk = blockIdx.x;
    const int bh = blk >> 1;
    const int half = blk & 1;
    const int b = bh >> 4, h = bh & 15;
    const int tid = threadIdx.x;
    const int d = half * 32 + (tid >> 2);
    const int qu = tid & 3;

    const float4* Sp = (const float4*)(S0 + ((size_t)bh * 64 + d) * 64 + qu * 16);
    float4 i0 = Sp[0], i1 = Sp[1], i2 = Sp[2], i3 = Sp[3];
    ull s_0, s_1, s_2, s_3, s_4, s_5, s_6, s_7;
    PK2(s_0, i0.x, i0.y); PK2(s_1, i0.z, i0.w);
    PK2(s_2, i1.x, i1.y); PK2(s_3, i1.z, i1.w);
    PK2(s_4, i2.x, i2.y); PK2(s_5, i2.z, i2.w);
    PK2(s_6, i3.x, i3.y); PK2(s_7, i3.z, i3.w);

    const size_t base = (size_t)b * DD + h * 64;
    const float* qb = g_proj + base;
    const float* kb = g_proj + (size_t)SEGC + base;
    const float* vb = g_proj + 2ull * SEGC + base;
    const size_t ob = (size_t)b * DD + h * 64 + d;

    float4 kr0_0, kr0_1, kr0_2, kr0_3, qr0_0, qr0_1, qr0_2, qr0_3;
    float4 kr1_0, kr1_1, kr1_2, kr1_3, qr1_0, qr1_1, qr1_2, qr1_3;
    float4 kr2_0, kr2_1, kr2_2, kr2_3, qr2_0, qr2_1, qr2_2, qr2_3;
    float4 kr3_0, kr3_1, kr3_2, kr3_3, qr3_0, qr3_1, qr3_2, qr3_3;
    float vr0, ar0, br0, vr1, ar1, br1, vr2, ar2, br2, vr3, ar3, br3;

    LOADS(0, 0); LOADS(1, 1); LOADS(2, 2); LOADS(3, 3);

    for (int t = 0; t < TT; t += 4) {
        STEP(0, t);
        STEP(1, t + 1);
        STEP(2, t + 2);
        STEP(3, t + 3);
    }

    float4 f0, f1, f2, f3;
    UNPK2(f0.x, f0.y, s_0); UNPK2(f0.z, f0.w, s_1);
    UNPK2(f1.x, f1.y, s_2); UNPK2(f1.z, f1.w, s_3);
    UNPK2(f2.x, f2.y, s_4); UNPK2(f2.z, f2.w, s_5);
    UNPK2(f3.x, f3.y, s_6); UNPK2(f3.z, f3.w, s_7);
    float4* So = (float4*)(out + (size_t)(TT * BB * DD) + ((size_t)bh * 64 + d) * 64 + qu * 16);
    So[0] = f0; So[1] = f1; So[2] = f2; So[3] = f3;
}

// =====================================================================
extern "C" void kernel_launch(void* const* d_in, const int* in_sizes, int n_in,
                              void* d_out, int out_size)
{
    const float* x  = (const float*)d_in[0];
    const float* S0 = (const float*)d_in[1];
    const float* Wq = (const float*)d_in[2];
    const float* Wk = (const float*)d_in[3];
    const float* Wv = (const float*)d_in[4];
    const float* Wa = (const float*)d_in[5];
    const float* ba = (const float*)d_in[6];
    const float* Wb = (const float*)d_in[7];
    const float* bb = (const float*)d_in[8];
    float* out = (float*)d_out;

    cudaFuncSetAttribute(gemm_mma, cudaFuncAttributeMaxDynamicSharedMemorySize, 4 * STG);

    pack_all<<<6656, 256>>>(x, Wq, Wk, Wv, Wa, Wb);
    gemm_mma<<<2560, 256, 4 * STG>>>(ba, bb);
    scan<<<256, 128>>>(S0, out);
}